// round 1
// baseline (speedup 1.0000x reference)
#include <cuda_runtime.h>
#include <math.h>

#define Bn 32          // batch
#define Nt 32          // targets per batch
#define Sg 52          // grid size
#define SS (Sg*Sg)     // 2704
#define Cc 80          // classes
#define CELLS (3*SS)   // cells per batch = 8112
#define NBLK_X 32      // ceil(8112/256)
#define NPART (Bn*NBLK_X + Bn)   // 1056 partials

// ANCHORS / stride (stride = 416/52 = 8); all values exact in binary
__constant__ float AW[9] = {14.5f, 19.5f, 46.625f, 3.75f, 7.75f, 7.375f, 1.25f, 2.0f, 4.125f};
__constant__ float AH[9] = {11.25f, 24.75f, 40.75f, 7.625f, 5.625f, 14.875f, 1.625f, 3.75f, 2.875f};

__device__ double g_part[NPART];
__device__ int    g_npos;

// Exact replica of reference _bce on sigmoid(z): p = clip(sigmoid(z)), -t log p - (1-t) log(1-p)
__device__ __forceinline__ float bce_t(float z, float t) {
    float p = 1.f / (1.f + expf(-z));
    p = fminf(fmaxf(p, 1e-7f), 1.f - 1e-7f);
    return -t * logf(p) - (1.f - t) * logf(1.f - p);
}

__global__ void k_init() { g_npos = 0; }

// ---------------------------------------------------------------------------
// Main kernel: for every cell (b,a,j,i) compute the "noobj" conf BCE term,
// gated by iou_max<=0.5 against the batch's 32 target boxes (smem).
// Masked cells are included here and corrected by k_corr.
// ---------------------------------------------------------------------------
__global__ void __launch_bounds__(256) k_noobj(const float* __restrict__ outp,
                                               const float* __restrict__ tgt) {
    __shared__ float tx1[Nt], tx2[Nt], ty1[Nt], ty2[Nt], tar[Nt];
    __shared__ float red[256];
    const int b = blockIdx.y;
    const int tid = threadIdx.x;

    if (tid < Nt) {
        const float* t = tgt + (b * Nt + tid) * 5;
        float gx = t[0] * 0.125f, gy = t[1] * 0.125f;
        float gw = t[2] * 0.125f, gh = t[3] * 0.125f;
        tx1[tid] = gx - gw * 0.5f; tx2[tid] = gx + gw * 0.5f;
        ty1[tid] = gy - gh * 0.5f; ty2[tid] = gy + gh * 0.5f;
        tar[tid] = gw * gh;
    }
    __syncthreads();

    const int m = blockIdx.x * 256 + tid;
    float contrib = 0.f;
    if (m < CELLS) {
        const int a = m / SS;
        const int rem = m - a * SS;
        const int j = rem / Sg;
        const int i = rem - j * Sg;
        const float* base = outp + (size_t)(b * 255 + a * 85) * SS + rem;
        const float zx = base[0];
        const float zy = base[SS];
        const float zw = base[2 * SS];
        const float zh = base[3 * SS];
        const float zc = base[4 * SS];

        const float px = 1.f / (1.f + expf(-zx)) + (float)i;
        const float py = 1.f / (1.f + expf(-zy)) + (float)j;
        const float pw = expf(zw) * AW[6 + a];
        const float ph = expf(zh) * AH[6 + a];
        const float bx1 = px - pw * 0.5f, bx2 = px + pw * 0.5f;
        const float by1 = py - ph * 0.5f, by2 = py + ph * 0.5f;
        const float ab = pw * ph;

        bool over = false;
        #pragma unroll 8
        for (int t2 = 0; t2 < Nt; t2++) {
            float iw = fmaxf(fminf(tx2[t2], bx2) - fmaxf(tx1[t2], bx1), 0.f);
            float ih = fmaxf(fminf(ty2[t2], by2) - fmaxf(ty1[t2], by1), 0.f);
            float inter = iw * ih;
            // iou > 0.5  <=>  3*inter > areaA + areaB  (division-free)
            if (3.f * inter > tar[t2] + ab) over = true;
        }
        if (!over) contrib = bce_t(zc, 0.f);
    }

    // deterministic block tree reduce
    red[tid] = contrib;
    __syncthreads();
    for (int s = 128; s > 0; s >>= 1) {
        if (tid < s) red[tid] += red[tid + s];
        __syncthreads();
    }
    if (tid == 0) g_part[b * NBLK_X + blockIdx.x] = (double)red[0];
}

// ---------------------------------------------------------------------------
// Correction kernel: one thread per target. Replicates the JAX scatter
// semantics: last valid target with a given flat index "wins" (mask/tx/ty/
// tw/th/box_loss_scale), while tcls is the union of one-hots of all valid
// colliding targets. The winner thread:
//   - undoes the noobj conf term added by k_noobj (if iou_max<=0.5 there)
//   - adds masked conf, x, y, w, h and class losses
// ---------------------------------------------------------------------------
__global__ void k_corr(const float* __restrict__ outp, const float* __restrict__ tgt) {
    __shared__ float sx1[Nt], sx2[Nt], sy1[Nt], sy2[Nt], sar[Nt];
    __shared__ int   sflat[Nt], scls[Nt], svalid[Nt];
    __shared__ double dred[Nt];

    const int b = blockIdx.x;
    const int n = threadIdx.x;

    const float* t = tgt + (b * Nt + n) * 5;
    const float gx = t[0] * 0.125f, gy = t[1] * 0.125f;
    const float gw = t[2] * 0.125f, gh = t[3] * 0.125f;
    sx1[n] = gx - gw * 0.5f; sx2[n] = gx + gw * 0.5f;
    sy1[n] = gy - gh * 0.5f; sy2[n] = gy + gh * 0.5f;
    sar[n] = gw * gh;

    // anchor argmax over 9 (first max wins, matching jnp.argmax)
    float bestr = -1e30f; int best = 0;
    #pragma unroll
    for (int q = 0; q < 9; q++) {
        float inter = fminf(gw, AW[q]) * fminf(gh, AH[q]);
        float uni = gw * gh + AW[q] * AH[q] - inter;
        float r = inter / uni;
        if (r > bestr) { bestr = r; best = q; }
    }
    const int valid = (best >= 6);
    const int k = best - 6;
    const int gi = (int)floorf(gx);
    const int gj = (int)floorf(gy);
    const int flat = ((b * 3 + k) * Sg + gj) * Sg + gi;

    sflat[n] = flat; svalid[n] = valid; scls[n] = (int)t[4];
    __syncthreads();

    double corr = 0.0;
    bool winner = (valid != 0);
    for (int q = n + 1; q < Nt; q++)
        if (svalid[q] && sflat[q] == flat) winner = false;

    if (winner) {
        atomicAdd(&g_npos, 1);

        const float txv = gx - (float)gi;
        const float tyv = gy - (float)gj;
        const float twv = logf(gw / AW[best]);
        const float thv = logf(gh / AH[best]);
        const float blsx = t[2] * (1.f / 416.f);
        const float blsy = t[3] * (1.f / 416.f);
        const float scale = 2.f - blsx * blsy;

        const int rem = gj * Sg + gi;
        const float* base = outp + (size_t)(b * 255 + k * 85) * SS + rem;
        const float zx = base[0];
        const float zy = base[SS];
        const float zw = base[2 * SS];
        const float zh = base[3 * SS];
        const float zc = base[4 * SS];

        // recompute the exact same iou flag as k_noobj at this cell
        const float px = 1.f / (1.f + expf(-zx)) + (float)gi;
        const float py = 1.f / (1.f + expf(-zy)) + (float)gj;
        const float pw = expf(zw) * AW[6 + k];
        const float ph = expf(zh) * AH[6 + k];
        const float bx1 = px - pw * 0.5f, bx2 = px + pw * 0.5f;
        const float by1 = py - ph * 0.5f, by2 = py + ph * 0.5f;
        const float ab = pw * ph;
        bool over = false;
        #pragma unroll 8
        for (int t2 = 0; t2 < Nt; t2++) {
            float iw = fmaxf(fminf(sx2[t2], bx2) - fmaxf(sx1[t2], bx1), 0.f);
            float ih = fmaxf(fminf(sy2[t2], by2) - fmaxf(sy1[t2], by1), 0.f);
            float inter = iw * ih;
            if (3.f * inter > sar[t2] + ab) over = true;
        }

        if (!over) corr -= (double)bce_t(zc, 0.f);   // undo noobj term
        corr += (double)bce_t(zc, 1.f);               // masked conf term
        corr += (double)(bce_t(zx, txv) * scale);
        corr += (double)(bce_t(zy, tyv) * scale);
        const float dw = zw - twv, dh = zh - thv;
        corr += (double)(0.5f * dw * dw * scale);
        corr += (double)(0.5f * dh * dh * scale);

        // class one-hot = union over all valid targets sharing this flat
        unsigned long long bits0 = 0ull, bits1 = 0ull;
        for (int q = 0; q < Nt; q++)
            if (svalid[q] && sflat[q] == flat) {
                int c = scls[q];
                if (c < 64) bits0 |= 1ull << c;
                else        bits1 |= 1ull << (c - 64);
            }
        for (int c = 0; c < Cc; c++) {
            float z = base[(5 + c) * SS];
            bool on = (c < 64) ? ((bits0 >> c) & 1ull) : ((bits1 >> (c - 64)) & 1ull);
            corr += (double)bce_t(z, on ? 1.f : 0.f);
        }
    }

    dred[n] = corr;
    __syncthreads();
    for (int s = 16; s > 0; s >>= 1) {
        if (n < s) dred[n] += dred[n + s];
        __syncthreads();
    }
    if (n == 0) g_part[Bn * NBLK_X + b] = dred[0];
}

// ---------------------------------------------------------------------------
// Finalize: fixed-order deterministic sum of the 1056 double partials.
// ---------------------------------------------------------------------------
__global__ void k_fin(float* __restrict__ res) {
    __shared__ double red[256];
    double s = 0.0;
    for (int idx = threadIdx.x; idx < NPART; idx += 256) s += g_part[idx];
    red[threadIdx.x] = s;
    __syncthreads();
    for (int q = 128; q > 0; q >>= 1) {
        if (threadIdx.x < q) red[threadIdx.x] += red[threadIdx.x + q];
        __syncthreads();
    }
    if (threadIdx.x == 0) {
        res[0] = (float)(red[0] * (1.0 / (double)Bn));
        res[1] = fmaxf((float)g_npos, 1.f);
    }
}

extern "C" void kernel_launch(void* const* d_in, const int* in_sizes, int n_in,
                              void* d_out, int out_size) {
    const float* outp = (const float*)d_in[0];
    const float* tgt  = (const float*)d_in[1];
    float* res = (float*)d_out;

    k_init<<<1, 1>>>();
    k_noobj<<<dim3(NBLK_X, Bn), 256>>>(outp, tgt);
    k_corr<<<Bn, Nt>>>(outp, tgt);
    k_fin<<<1, 256>>>(res);
}

// round 2
// speedup vs baseline: 1.8384x; 1.8384x over previous
#include <cuda_runtime.h>
#include <math.h>

#define Bn 32          // batch
#define Nt 32          // targets per batch
#define Sg 52          // grid size
#define SS (Sg*Sg)     // 2704
#define Cc 80          // classes
#define CELLS (3*SS)   // 8112 cells per batch
#define NBX 32         // noobj blocks per batch (ceil(8112/256))
#define TOTB ((NBX+1)*Bn)        // 1056 blocks total
#define NPART (Bn*NBX + Bn)      // 1056 double partials

// ANCHORS / stride (stride = 8); exact in binary
__constant__ float AW[9] = {14.5f, 19.5f, 46.625f, 3.75f, 7.75f, 7.375f, 1.25f, 2.0f, 4.125f};
__constant__ float AH[9] = {11.25f, 24.75f, 40.75f, 7.625f, 5.625f, 14.875f, 1.625f, 3.75f, 2.875f};

__device__ double       g_part[NPART];
__device__ int          g_nposi[Bn];
__device__ unsigned int g_ctr;   // zero-initialized; reset by final block each run

// Fast BCE on sigmoid(z) with the reference's 1e-7 clip. Used IDENTICALLY in
// the noobj path and the corr undo path so the subtraction cancels exactly.
__device__ __forceinline__ float sig_fast(float z) {
    return __fdividef(1.f, 1.f + __expf(-z));
}
__device__ __forceinline__ float bce0(float z) {           // t = 0
    float p = sig_fast(z);
    p = fminf(fmaxf(p, 1e-7f), 1.f - 1e-7f);
    return -__logf(1.f - p);
}
__device__ __forceinline__ float bce1(float z) {           // t = 1
    float p = sig_fast(z);
    p = fminf(fmaxf(p, 1e-7f), 1.f - 1e-7f);
    return -__logf(p);
}
__device__ __forceinline__ float bce_t(float z, float t) { // general t
    float p = sig_fast(z);
    p = fminf(fmaxf(p, 1e-7f), 1.f - 1e-7f);
    return -t * __logf(p) - (1.f - t) * __logf(1.f - p);
}

// Shared IoU>0.5 test (division-free: iou>0.5 <=> 3*inter > areaA+areaB).
// Same code object for noobj and corr so the gating bit matches bit-for-bit.
__device__ __forceinline__ bool iou_over(const float4* __restrict__ tb,
                                         const float*  __restrict__ tar,
                                         float bx1, float by1, float bx2, float by2,
                                         float ab) {
    float m = -1.f;
    #pragma unroll 8
    for (int t = 0; t < Nt; t++) {
        float4 q = tb[t];                         // {x1,y1,x2,y2} -> one LDS.128
        float iw = fmaxf(fminf(q.z, bx2) - fmaxf(q.x, bx1), 0.f);
        float ih = fmaxf(fminf(q.w, by2) - fmaxf(q.y, by1), 0.f);
        float inter = iw * ih;
        m = fmaxf(m, __fmaf_rn(3.f, inter, -(tar[t] + ab)));
    }
    return m > 0.f;
}

__global__ void __launch_bounds__(256) k_fused(const float* __restrict__ outp,
                                               const float* __restrict__ tgt,
                                               float* __restrict__ res) {
    __shared__ float4 tb[Nt];
    __shared__ float  tar[Nt];
    __shared__ float  red[256];
    __shared__ double dred[256];
    __shared__ int    sflat[Nt], scls[Nt], svalid[Nt];
    __shared__ int    lastflag;

    const int b   = blockIdx.y;
    const int bx  = blockIdx.x;
    const int tid = threadIdx.x;

    if (tid < Nt) {
        const float* t = tgt + (b * Nt + tid) * 5;
        float gx = t[0] * 0.125f, gy = t[1] * 0.125f;
        float gw = t[2] * 0.125f, gh = t[3] * 0.125f;
        tb[tid]  = make_float4(gx - gw * 0.5f, gy - gh * 0.5f,
                               gx + gw * 0.5f, gy + gh * 0.5f);
        tar[tid] = gw * gh;
    }
    if (tid == 0) lastflag = 0;
    __syncthreads();

    if (bx < NBX) {
        // ----------------- noobj pass: one thread per cell -----------------
        const int m = bx * 256 + tid;
        float contrib = 0.f;
        if (m < CELLS) {
            const int a   = m / SS;
            const int rem = m - a * SS;
            const int j   = rem / Sg;
            const int i   = rem - j * Sg;
            const float* base = outp + (size_t)(b * 255 + a * 85) * SS + rem;
            const float zx = base[0];
            const float zy = base[SS];
            const float zw = base[2 * SS];
            const float zh = base[3 * SS];
            const float zc = base[4 * SS];

            const float px = sig_fast(zx) + (float)i;
            const float py = sig_fast(zy) + (float)j;
            const float pw = __expf(zw) * AW[6 + a];
            const float ph = __expf(zh) * AH[6 + a];
            const float hw = pw * 0.5f, hh = ph * 0.5f;
            bool over = iou_over(tb, tar, px - hw, py - hh, px + hw, py + hh, pw * ph);
            if (!over) contrib = bce0(zc);
        }
        red[tid] = contrib;
        __syncthreads();
        #pragma unroll
        for (int s = 128; s > 0; s >>= 1) {
            if (tid < s) red[tid] += red[tid + s];
            __syncthreads();
        }
        if (tid == 0) g_part[b * NBX + bx] = (double)red[0];
    } else {
        // ----------------- correction pass: warp 0, one thread/target ------
        if (tid < Nt) {
            const int n = tid;
            const float* t = tgt + (b * Nt + n) * 5;
            const float gx = t[0] * 0.125f, gy = t[1] * 0.125f;
            const float gw = t[2] * 0.125f, gh = t[3] * 0.125f;

            // anchor argmax over 9 (first max wins, matching jnp.argmax)
            float bestr = -1e30f; int best = 0;
            #pragma unroll
            for (int q = 0; q < 9; q++) {
                float inter = fminf(gw, AW[q]) * fminf(gh, AH[q]);
                float uni   = gw * gh + AW[q] * AH[q] - inter;
                float r = inter / uni;
                if (r > bestr) { bestr = r; best = q; }
            }
            const int valid = (best >= 6);
            const int k  = best - 6;
            const int gi = (int)floorf(gx);
            const int gj = (int)floorf(gy);
            const int flat = ((b * 3 + k) * Sg + gj) * Sg + gi;
            sflat[n] = flat; svalid[n] = valid; scls[n] = (int)t[4];
            __syncwarp();

            double corr = 0.0;
            bool winner = (valid != 0);
            for (int q = n + 1; q < Nt; q++)
                if (svalid[q] && sflat[q] == flat) winner = false;

            if (winner) {
                const float txv = gx - (float)gi;
                const float tyv = gy - (float)gj;
                const float twv = __logf(gw / AW[best]);
                const float thv = __logf(gh / AH[best]);
                const float scale = 2.f - (t[2] * (1.f / 416.f)) * (t[3] * (1.f / 416.f));

                const int rem = gj * Sg + gi;
                const float* base = outp + (size_t)(b * 255 + k * 85) * SS + rem;
                const float zx = base[0];
                const float zy = base[SS];
                const float zw = base[2 * SS];
                const float zh = base[3 * SS];
                const float zc = base[4 * SS];

                // recompute the exact same over flag as the noobj pass
                const float px = sig_fast(zx) + (float)gi;
                const float py = sig_fast(zy) + (float)gj;
                const float pw = __expf(zw) * AW[6 + k];
                const float ph = __expf(zh) * AH[6 + k];
                const float hw = pw * 0.5f, hh = ph * 0.5f;
                bool over = iou_over(tb, tar, px - hw, py - hh, px + hw, py + hh, pw * ph);

                if (!over) corr -= (double)bce0(zc);   // undo noobj term
                corr += (double)bce1(zc);              // masked conf term
                corr += (double)(bce_t(zx, txv) * scale);
                corr += (double)(bce_t(zy, tyv) * scale);
                const float dw = zw - twv, dh = zh - thv;
                corr += (double)(0.5f * dw * dw * scale);
                corr += (double)(0.5f * dh * dh * scale);

                // class one-hot = union over valid targets sharing this flat
                unsigned long long bits0 = 0ull, bits1 = 0ull;
                for (int q = 0; q < Nt; q++)
                    if (svalid[q] && sflat[q] == flat) {
                        int c = scls[q];
                        if (c < 64) bits0 |= 1ull << c;
                        else        bits1 |= 1ull << (c - 64);
                    }
                for (int c = 0; c < Cc; c++) {
                    float z = base[(5 + c) * SS];
                    bool on = (c < 64) ? ((bits0 >> c) & 1ull)
                                       : ((bits1 >> (c - 64)) & 1ull);
                    corr += (double)bce_t(z, on ? 1.f : 0.f);
                }
            }

            // warp-level fixed-order reduce + winner count
            unsigned bal = __ballot_sync(0xffffffffu, winner);
            #pragma unroll
            for (int s = 16; s > 0; s >>= 1)
                corr += __shfl_down_sync(0xffffffffu, corr, s);
            if (n == 0) {
                g_part[Bn * NBX + b] = corr;
                g_nposi[b] = __popc(bal);
            }
        }
    }

    // ----------------- last-block-done finalize -----------------
    if (tid == 0) {
        __threadfence();
        if (atomicAdd(&g_ctr, 1u) == TOTB - 1) lastflag = 1;
    }
    __syncthreads();
    if (lastflag) {
        double s = 0.0;
        for (int i = tid; i < NPART; i += 256) s += g_part[i];
        dred[tid] = s;
        __syncthreads();
        #pragma unroll
        for (int q = 128; q > 0; q >>= 1) {
            if (tid < q) dred[tid] += dred[tid + q];
            __syncthreads();
        }
        int np = (tid < Bn) ? g_nposi[tid] : 0;
        #pragma unroll
        for (int s2 = 16; s2 > 0; s2 >>= 1)
            np += __shfl_down_sync(0xffffffffu, np, s2);
        if (tid == 0) {
            res[0] = (float)(dred[0] * (1.0 / (double)Bn));
            res[1] = fmaxf((float)np, 1.f);
            g_ctr = 0u;   // reset for next graph replay
        }
    }
}

extern "C" void kernel_launch(void* const* d_in, const int* in_sizes, int n_in,
                              void* d_out, int out_size) {
    const float* outp = (const float*)d_in[0];
    const float* tgt  = (const float*)d_in[1];
    float* res = (float*)d_out;
    k_fused<<<dim3(NBX + 1, Bn), 256>>>(outp, tgt, res);
}

// round 3
// speedup vs baseline: 2.0247x; 1.1013x over previous
#include <cuda_runtime.h>
#include <math.h>

#define Bn 32          // batch
#define Nt 32          // targets per batch
#define Sg 52          // grid size
#define SS (Sg*Sg)     // 2704
#define Cc 80          // classes
#define CELLS (3*SS)   // 8112 cells per batch
#define CPT 4          // cells per thread
#define GRPS (CELLS/CPT)   // 2028 cell-groups per batch
#define NBX 8          // noobj blocks per batch (8*256*4 = 8192 >= 8112)
#define TOTB ((NBX+1)*Bn)        // 288 blocks total
#define NPART (Bn*NBX + Bn)      // 288 double partials

// ANCHORS / stride (stride = 8); exact in binary
__constant__ float AW[9] = {14.5f, 19.5f, 46.625f, 3.75f, 7.75f, 7.375f, 1.25f, 2.0f, 4.125f};
__constant__ float AH[9] = {11.25f, 24.75f, 40.75f, 7.625f, 5.625f, 14.875f, 1.625f, 3.75f, 2.875f};

__device__ double       g_part[NPART];
__device__ int          g_nposi[Bn];
__device__ unsigned int g_ctr;   // zero-init; reset by the finalize block

// Fast BCE on sigmoid(z) with the reference's 1e-7 clip. Used identically in
// the noobj path and the corr undo path so the subtraction cancels exactly.
__device__ __forceinline__ float sig_fast(float z) {
    return __fdividef(1.f, 1.f + __expf(-z));
}
__device__ __forceinline__ float bce0(float z) {           // t = 0
    float p = sig_fast(z);
    p = fminf(fmaxf(p, 1e-7f), 1.f - 1e-7f);
    return -__logf(1.f - p);
}
__device__ __forceinline__ float bce1(float z) {           // t = 1
    float p = sig_fast(z);
    p = fminf(fmaxf(p, 1e-7f), 1.f - 1e-7f);
    return -__logf(p);
}
__device__ __forceinline__ float bce_t(float z, float t) { // general t
    float p = sig_fast(z);
    p = fminf(fmaxf(p, 1e-7f), 1.f - 1e-7f);
    return -t * __logf(p) - (1.f - t) * __logf(1.f - p);
}

// Scalar IoU>0.5 test for ONE cell. over <=> max_t(3*inter - tar_t) > ab.
// The vectorized noobj loop performs the exact same per-cell op sequence so
// the corr pass reproduces the flag bit-for-bit.
__device__ __forceinline__ bool iou_over1(const float4* __restrict__ tb,
                                          const float*  __restrict__ tar,
                                          float bx1, float by1, float bx2, float by2,
                                          float ab) {
    float m = -1e30f;
    #pragma unroll 8
    for (int t = 0; t < Nt; t++) {
        float4 q = tb[t];
        float iw = fmaxf(fminf(q.z, bx2) - fmaxf(q.x, bx1), 0.f);
        float ih = fmaxf(fminf(q.w, by2) - fmaxf(q.y, by1), 0.f);
        m = fmaxf(m, __fmaf_rn(3.f, iw * ih, -tar[t]));
    }
    return m > ab;
}

__global__ void __launch_bounds__(256) k_fused(const float* __restrict__ outp,
                                               const float* __restrict__ tgt,
                                               float* __restrict__ res) {
    __shared__ float4 tb[Nt];
    __shared__ float  tar[Nt];
    __shared__ float  wred[8];
    __shared__ double dred[256];
    __shared__ int    sflat[Nt], scls[Nt], svalid[Nt];
    __shared__ int    lastflag;

    const int b    = blockIdx.y;
    const int bx   = blockIdx.x;
    const int tid  = threadIdx.x;
    const int lane = tid & 31;
    const int wid  = tid >> 5;

    if (tid < Nt) {
        const float* t = tgt + (b * Nt + tid) * 5;
        float gx = t[0] * 0.125f, gy = t[1] * 0.125f;
        float gw = t[2] * 0.125f, gh = t[3] * 0.125f;
        tb[tid]  = make_float4(gx - gw * 0.5f, gy - gh * 0.5f,
                               gx + gw * 0.5f, gy + gh * 0.5f);
        tar[tid] = gw * gh;
    }
    if (tid == 0) lastflag = 0;
    __syncthreads();

    if (bx < NBX) {
        // ------------- noobj pass: 4 consecutive cells per thread -------------
        const int g = bx * 256 + tid;          // cell group index
        float contrib = 0.f;
        if (g < GRPS) {
            const int m0   = g * CPT;
            const int a    = m0 / SS;          // same anchor for all 4 (SS%4==0)
            const int rem0 = m0 - a * SS;
            const int j    = rem0 / Sg;        // same row for all 4 (Sg%4==0)
            const int i0   = rem0 - j * Sg;

            const float* base = outp + (size_t)(b * 255 + a * 85) * SS + rem0;
            const float4 zx4 = *(const float4*)(base);
            const float4 zy4 = *(const float4*)(base + SS);
            const float4 zw4 = *(const float4*)(base + 2 * SS);
            const float4 zh4 = *(const float4*)(base + 3 * SS);
            const float4 zc4 = *(const float4*)(base + 4 * SS);
            const float zx[4] = {zx4.x, zx4.y, zx4.z, zx4.w};
            const float zy[4] = {zy4.x, zy4.y, zy4.z, zy4.w};
            const float zw[4] = {zw4.x, zw4.y, zw4.z, zw4.w};
            const float zh[4] = {zh4.x, zh4.y, zh4.z, zh4.w};
            const float zc[4] = {zc4.x, zc4.y, zc4.z, zc4.w};

            const float awa = AW[6 + a], aha = AH[6 + a];
            float bx1[4], by1[4], bx2[4], by2[4], ab[4], mm[4];
            #pragma unroll
            for (int c = 0; c < CPT; c++) {
                float px = sig_fast(zx[c]) + (float)(i0 + c);
                float py = sig_fast(zy[c]) + (float)j;
                float pw = __expf(zw[c]) * awa;
                float ph = __expf(zh[c]) * aha;
                float hw = pw * 0.5f, hh = ph * 0.5f;
                bx1[c] = px - hw; bx2[c] = px + hw;
                by1[c] = py - hh; by2[c] = py + hh;
                ab[c]  = pw * ph;
                mm[c]  = -1e30f;
            }

            #pragma unroll 8
            for (int t = 0; t < Nt; t++) {
                const float4 q  = tb[t];
                const float  ta = tar[t];
                #pragma unroll
                for (int c = 0; c < CPT; c++) {
                    float iw = fmaxf(fminf(q.z, bx2[c]) - fmaxf(q.x, bx1[c]), 0.f);
                    float ih = fmaxf(fminf(q.w, by2[c]) - fmaxf(q.y, by1[c]), 0.f);
                    mm[c] = fmaxf(mm[c], __fmaf_rn(3.f, iw * ih, -ta));
                }
            }
            #pragma unroll
            for (int c = 0; c < CPT; c++)
                if (!(mm[c] > ab[c])) contrib += bce0(zc[c]);
        }

        // shuffle + cross-warp reduce (deterministic)
        #pragma unroll
        for (int s = 16; s > 0; s >>= 1)
            contrib += __shfl_down_sync(0xffffffffu, contrib, s);
        if (lane == 0) wred[wid] = contrib;
        __syncthreads();
        if (tid == 0) {
            float s = 0.f;
            #pragma unroll
            for (int q = 0; q < 8; q++) s += wred[q];
            g_part[b * NBX + bx] = (double)s;
        }
    } else {
        // ------------- correction pass: warp 0, one thread per target -------------
        if (tid < Nt) {
            const int n = tid;
            const float* t = tgt + (b * Nt + n) * 5;
            const float gx = t[0] * 0.125f, gy = t[1] * 0.125f;
            const float gw = t[2] * 0.125f, gh = t[3] * 0.125f;

            // anchor argmax over 9 (first max wins, matching jnp.argmax)
            float bestr = -1e30f; int best = 0;
            #pragma unroll
            for (int q = 0; q < 9; q++) {
                float inter = fminf(gw, AW[q]) * fminf(gh, AH[q]);
                float uni   = gw * gh + AW[q] * AH[q] - inter;
                float r = inter / uni;
                if (r > bestr) { bestr = r; best = q; }
            }
            const int valid = (best >= 6);
            const int k  = best - 6;
            const int gi = (int)floorf(gx);
            const int gj = (int)floorf(gy);
            const int flat = ((b * 3 + k) * Sg + gj) * Sg + gi;
            sflat[n] = flat; svalid[n] = valid; scls[n] = (int)t[4];
            __syncwarp();

            double corr = 0.0;
            bool winner = (valid != 0);
            for (int q = n + 1; q < Nt; q++)
                if (svalid[q] && sflat[q] == flat) winner = false;

            if (winner) {
                const float txv = gx - (float)gi;
                const float tyv = gy - (float)gj;
                const float twv = __logf(gw / AW[best]);
                const float thv = __logf(gh / AH[best]);
                const float scale = 2.f - (t[2] * (1.f / 416.f)) * (t[3] * (1.f / 416.f));

                const int rem = gj * Sg + gi;
                const float* base = outp + (size_t)(b * 255 + k * 85) * SS + rem;
                const float zx = base[0];
                const float zy = base[SS];
                const float zw = base[2 * SS];
                const float zh = base[3 * SS];
                const float zc = base[4 * SS];

                // identical op sequence to the noobj pass -> same flag
                const float px = sig_fast(zx) + (float)gi;
                const float py = sig_fast(zy) + (float)gj;
                const float pw = __expf(zw) * AW[6 + k];
                const float ph = __expf(zh) * AH[6 + k];
                const float hw = pw * 0.5f, hh = ph * 0.5f;
                bool over = iou_over1(tb, tar, px - hw, py - hh, px + hw, py + hh, pw * ph);

                if (!over) corr -= (double)bce0(zc);   // undo noobj term
                corr += (double)bce1(zc);              // masked conf term
                corr += (double)(bce_t(zx, txv) * scale);
                corr += (double)(bce_t(zy, tyv) * scale);
                const float dw = zw - twv, dh = zh - thv;
                corr += (double)(0.5f * dw * dw * scale);
                corr += (double)(0.5f * dh * dh * scale);

                // class one-hot = union over valid targets sharing this flat
                unsigned long long bits0 = 0ull, bits1 = 0ull;
                for (int q = 0; q < Nt; q++)
                    if (svalid[q] && sflat[q] == flat) {
                        int c = scls[q];
                        if (c < 64) bits0 |= 1ull << c;
                        else        bits1 |= 1ull << (c - 64);
                    }
                for (int c = 0; c < Cc; c++) {
                    float z = base[(5 + c) * SS];
                    bool on = (c < 64) ? ((bits0 >> c) & 1ull)
                                       : ((bits1 >> (c - 64)) & 1ull);
                    corr += (double)bce_t(z, on ? 1.f : 0.f);
                }
            }

            unsigned bal = __ballot_sync(0xffffffffu, winner);
            #pragma unroll
            for (int s = 16; s > 0; s >>= 1)
                corr += __shfl_down_sync(0xffffffffu, corr, s);
            if (n == 0) {
                g_part[Bn * NBX + b] = corr;
                g_nposi[b] = __popc(bal);
            }
        }
    }

    // ------------- last-block-done finalize -------------
    if (tid == 0) {
        __threadfence();
        if (atomicAdd(&g_ctr, 1u) == TOTB - 1) lastflag = 1;
    }
    __syncthreads();
    if (lastflag) {
        double s = 0.0;
        for (int i = tid; i < NPART; i += 256) s += g_part[i];
        dred[tid] = s;
        __syncthreads();
        #pragma unroll
        for (int q = 128; q > 0; q >>= 1) {
            if (tid < q) dred[tid] += dred[tid + q];
            __syncthreads();
        }
        int np = (tid < Bn) ? g_nposi[tid] : 0;
        #pragma unroll
        for (int s2 = 16; s2 > 0; s2 >>= 1)
            np += __shfl_down_sync(0xffffffffu, np, s2);
        if (tid == 0) {
            res[0] = (float)(dred[0] * (1.0 / (double)Bn));
            res[1] = fmaxf((float)np, 1.f);
            g_ctr = 0u;   // reset for next graph replay
        }
    }
}

extern "C" void kernel_launch(void* const* d_in, const int* in_sizes, int n_in,
                              void* d_out, int out_size) {
    const float* outp = (const float*)d_in[0];
    const float* tgt  = (const float*)d_in[1];
    float* res = (float*)d_out;
    k_fused<<<dim3(NBX + 1, Bn), 256>>>(outp, tgt, res);
}